// round 1
// baseline (speedup 1.0000x reference)
#include <cuda_runtime.h>

#define HW     4096
#define WIDTH  64
#define CDIM   256
#define NH     8
#define HD     32
#define BATCH  2
#define SCALE  0.17677669529663687f

// Scratch (device globals; no allocation allowed)
__device__ float g_q[BATCH * NH * HW * HD];      // [b, head, p, d]
__device__ float g_k[BATCH * NH * HW * HD];      // [b, head, p, d]
__device__ float g_v[BATCH * NH * HW * HD];      // [b, head, p, d]
__device__ float g_attn[BATCH * HW * CDIM];      // [b, p, c]  c = head*32+d

// ---------------------------------------------------------------------------
// Kernel 1: QKV projection. Effective GEMM M=768 (3 types x 8 heads x 32 d),
// K=256, N=4096 per batch. Each output row pulls from the weight tensor of the
// range that owns its head. Output written transposed into [b,head,p,d].
// ---------------------------------------------------------------------------
__global__ __launch_bounds__(256) void qkv_gemm_kernel(
    const float* __restrict__ x,
    const float* __restrict__ w0, const float* __restrict__ bb0,
    const float* __restrict__ w1, const float* __restrict__ bb1,
    const float* __restrict__ w2, const float* __restrict__ bb2)
{
    __shared__ float As[64][16];
    __shared__ float Bs[16][68];
    __shared__ const float* Arow[64];
    __shared__ float biasS[64];

    const int tid  = threadIdx.x;
    const int row0 = blockIdx.y * 64;
    const int col0 = blockIdx.x * 64;
    const int b    = blockIdx.z;

    if (tid < 64) {
        int M = row0 + tid;
        int t = M >> 8;            // 0=q, 1=k, 2=v
        int rem = M & 255;         // head*32 + d
        int head = rem >> 5;
        const float* w; const float* bb;
        if (head < 4)      { w = w0; bb = bb0; }
        else if (head < 7) { w = w1; bb = bb1; }
        else               { w = w2; bb = bb2; }
        Arow[tid]  = w + (size_t)(t * 256 + rem) * 256;
        biasS[tid] = bb[t * 256 + rem];
    }
    __syncthreads();

    const int tx = tid & 15, ty = tid >> 4;
    float acc[4][4] = {};
    const float* xb = x + (size_t)b * CDIM * HW;

    for (int k0 = 0; k0 < 256; k0 += 16) {
        {   // load A tile (64x16): one float4 per thread
            int m = tid >> 2, k = (tid & 3) * 4;
            float4 av = *(const float4*)(Arow[m] + k0 + k);
            *(float4*)&As[m][k] = av;
        }
        {   // load B tile (16x64): one float4 per thread, coalesced along n
            int k = tid >> 4, n = (tid & 15) * 4;
            float4 bv = *(const float4*)(xb + (size_t)(k0 + k) * HW + col0 + n);
            *(float4*)&Bs[k][n] = bv;
        }
        __syncthreads();
        #pragma unroll
        for (int kk = 0; kk < 16; kk++) {
            float a[4];
            #pragma unroll
            for (int i = 0; i < 4; i++) a[i] = As[ty * 4 + i][kk];
            float4 bv = *(float4*)&Bs[kk][tx * 4];
            float bl[4] = {bv.x, bv.y, bv.z, bv.w};
            #pragma unroll
            for (int i = 0; i < 4; i++)
                #pragma unroll
                for (int j = 0; j < 4; j++)
                    acc[i][j] += a[i] * bl[j];
        }
        __syncthreads();
    }

    #pragma unroll
    for (int i = 0; i < 4; i++) {
        int M = row0 + ty * 4 + i;
        int t = M >> 8, rem = M & 255, head = rem >> 5, d = rem & 31;
        float* dst = (t == 0) ? g_q : (t == 1) ? g_k : g_v;
        float bias = biasS[ty * 4 + i];
        int base = ((b * NH + head) * HW) * HD + d;
        #pragma unroll
        for (int j = 0; j < 4; j++) {
            int p = col0 + tx * 4 + j;
            dst[base + p * HD] = acc[i][j] + bias;
        }
    }
}

// ---------------------------------------------------------------------------
// Kernel 2: neighborhood attention. One warp per (b, head, pixel); lane = d.
// OOB neighbors (F.unfold zero padding) contribute logit = q.0 = 0 and v = 0,
// but remain inside the softmax.
// ---------------------------------------------------------------------------
template <int KSZ, int DIL>
__device__ __forceinline__ void attn_body(
    int lane, int b, int head, int p)
{
    constexpr int L = KSZ * KSZ;
    constexpr int NL = (L + 31) / 32;
    constexpr int HALF = KSZ / 2;

    const int y = p >> 6, x = p & 63;
    const int hb = ((b * NH + head) * HW) * HD;
    const float* __restrict__ kb = g_k + hb;
    const float* __restrict__ vb = g_v + hb;

    const float q = g_q[hb + p * HD + lane] * SCALE;

    float lgs[NL];
    #pragma unroll
    for (int j = 0; j < NL; j++) lgs[j] = 0.f;

    #pragma unroll
    for (int ky = 0; ky < KSZ; ky++) {
        const int ny = y + (ky - HALF) * DIL;
        #pragma unroll
        for (int kx = 0; kx < KSZ; kx++) {
            const int l = ky * KSZ + kx;
            const int nx = x + (kx - HALF) * DIL;
            float s = 0.f;
            if ((unsigned)ny < 64u && (unsigned)nx < 64u)
                s = q * kb[(ny * 64 + nx) * HD + lane];
            #pragma unroll
            for (int o = 16; o > 0; o >>= 1)
                s += __shfl_xor_sync(0xffffffffu, s, o);
            if ((l & 31) == lane) lgs[l >> 5] = s;
        }
    }

    float mx = -1e30f;
    #pragma unroll
    for (int j = 0; j < NL; j++)
        if (j * 32 + lane < L) mx = fmaxf(mx, lgs[j]);
    #pragma unroll
    for (int o = 16; o > 0; o >>= 1)
        mx = fmaxf(mx, __shfl_xor_sync(0xffffffffu, mx, o));

    float e[NL];
    float sum = 0.f;
    #pragma unroll
    for (int j = 0; j < NL; j++) {
        e[j] = (j * 32 + lane < L) ? __expf(lgs[j] - mx) : 0.f;
        sum += e[j];
    }
    #pragma unroll
    for (int o = 16; o > 0; o >>= 1)
        sum += __shfl_xor_sync(0xffffffffu, sum, o);
    const float inv = 1.f / sum;

    float acc = 0.f;
    #pragma unroll
    for (int ky = 0; ky < KSZ; ky++) {
        const int ny = y + (ky - HALF) * DIL;
        #pragma unroll
        for (int kx = 0; kx < KSZ; kx++) {
            const int l = ky * KSZ + kx;
            const int nx = x + (kx - HALF) * DIL;
            if ((unsigned)ny < 64u && (unsigned)nx < 64u) {
                float pl = __shfl_sync(0xffffffffu, e[l >> 5], l & 31) * inv;
                acc += pl * vb[(ny * 64 + nx) * HD + lane];
            }
        }
    }

    g_attn[(b * HW + p) * CDIM + head * HD + lane] = acc;
}

__global__ __launch_bounds__(256) void attn_kernel()
{
    const int lane = threadIdx.x & 31;
    const int wid  = threadIdx.x >> 5;
    const int W    = blockIdx.x * 8 + wid;
    const int p    = W & (HW - 1);
    const int head = (W >> 12) & 7;
    const int b    = W >> 15;

    if (head < 4)      attn_body<5, 1>(lane, b, head, p);
    else if (head < 7) attn_body<7, 2>(lane, b, head, p);
    else               attn_body<9, 3>(lane, b, head, p);
}

// ---------------------------------------------------------------------------
// Kernel 3: output projection. out[b,o,p] = sum_c attn[b,p,c]*pw[o,c] + pb[o].
// M=256, K=256, N=4096 per batch.
// ---------------------------------------------------------------------------
__global__ __launch_bounds__(256) void proj_gemm_kernel(
    const float* __restrict__ pw, const float* __restrict__ pb,
    float* __restrict__ out)
{
    __shared__ float As[64][16];
    __shared__ float Bs[16][68];

    const int tid  = threadIdx.x;
    const int row0 = blockIdx.y * 64;
    const int col0 = blockIdx.x * 64;
    const int b    = blockIdx.z;

    const int tx = tid & 15, ty = tid >> 4;
    float acc[4][4] = {};
    const float* attb = g_attn + (size_t)b * HW * CDIM;

    for (int k0 = 0; k0 < 256; k0 += 16) {
        {   // A tile: proj_w rows
            int m = tid >> 2, k = (tid & 3) * 4;
            *(float4*)&As[m][k] =
                *(const float4*)(pw + (size_t)(row0 + m) * 256 + k0 + k);
        }
        {   // B tile: attn is [p, c] -> transpose into Bs[k][n]
            int n = tid >> 2, k = (tid & 3) * 4;
            float4 bv = *(const float4*)(attb + (size_t)(col0 + n) * CDIM + k0 + k);
            Bs[k][n]     = bv.x;
            Bs[k + 1][n] = bv.y;
            Bs[k + 2][n] = bv.z;
            Bs[k + 3][n] = bv.w;
        }
        __syncthreads();
        #pragma unroll
        for (int kk = 0; kk < 16; kk++) {
            float a[4];
            #pragma unroll
            for (int i = 0; i < 4; i++) a[i] = As[ty * 4 + i][kk];
            float4 bv = *(float4*)&Bs[kk][tx * 4];
            float bl[4] = {bv.x, bv.y, bv.z, bv.w};
            #pragma unroll
            for (int i = 0; i < 4; i++)
                #pragma unroll
                for (int j = 0; j < 4; j++)
                    acc[i][j] += a[i] * bl[j];
        }
        __syncthreads();
    }

    #pragma unroll
    for (int i = 0; i < 4; i++) {
        int o = row0 + ty * 4 + i;
        float bias = pb[o];
        float4 ov = make_float4(acc[i][0] + bias, acc[i][1] + bias,
                                acc[i][2] + bias, acc[i][3] + bias);
        *(float4*)(out + ((size_t)b * CDIM + o) * HW + col0 + tx * 4) = ov;
    }
}

// ---------------------------------------------------------------------------
extern "C" void kernel_launch(void* const* d_in, const int* in_sizes, int n_in,
                              void* d_out, int out_size)
{
    const float* x   = (const float*)d_in[0];
    const float* w0  = (const float*)d_in[1];
    const float* bb0 = (const float*)d_in[2];
    const float* w1  = (const float*)d_in[3];
    const float* bb1 = (const float*)d_in[4];
    const float* w2  = (const float*)d_in[5];
    const float* bb2 = (const float*)d_in[6];
    const float* pw  = (const float*)d_in[7];
    const float* pb  = (const float*)d_in[8];
    float* out = (float*)d_out;

    qkv_gemm_kernel<<<dim3(HW / 64, 768 / 64, BATCH), 256>>>(
        x, w0, bb0, w1, bb1, w2, bb2);

    attn_kernel<<<(BATCH * NH * HW) / 8, 256>>>();

    proj_gemm_kernel<<<dim3(HW / 64, CDIM / 64, BATCH), 256>>>(pw, pb, out);
}